// round 1
// baseline (speedup 1.0000x reference)
#include <cuda_runtime.h>

#define HID 256
#define LC 512
#define NCH 256
#define PLANE (HID*LC)   // 131072 floats per chunk

// Ping-pong activation buffers (128 MiB each) — static device memory, no allocation.
__device__ float g_bufA[(size_t)NCH * PLANE];
__device__ float g_bufB[(size_t)NCH * PLANE];

__device__ __forceinline__ float gelu_res(float c) {
    // gelu(c, approximate=False) + c
    return fmaf(0.5f * c, 1.0f + erff(c * 0.70710678118654752440f), c);
}

// ---------------------------------------------------------------------------
// Projection: out[n][c][l] = sum_m x[row][m] * w_proj[c][m], row = n*512+l
// GEMM 131072 x 256 x 283, 64x64 tiles, 4x4 per thread. Writes g_bufA.
// ---------------------------------------------------------------------------
__global__ __launch_bounds__(256) void proj_kernel(const float* __restrict__ x,
                                                   const float* __restrict__ wp) {
    __shared__ float As[16][65];  // [kk][c]   (65: avoid store bank conflicts)
    __shared__ float Bs[16][68];  // [kk][r]   (68: 16B-aligned rows, conflict-free)
    const int rbase = blockIdx.x * 64;
    const int cbase = blockIdx.y * 64;
    const int tid = threadIdx.x;
    const int tx = tid & 15, ty = tid >> 4;

    float acc[4][4];
#pragma unroll
    for (int i = 0; i < 4; i++)
#pragma unroll
        for (int j = 0; j < 4; j++) acc[i][j] = 0.f;

    for (int kb = 0; kb < 283; kb += 16) {
#pragma unroll
        for (int e = 0; e < 4; e++) {
            int idx = tid + e * 256;
            int c = idx >> 4, kk = idx & 15;
            int m = kb + kk;
            As[kk][c] = (m < 283) ? wp[(cbase + c) * 283 + m] : 0.f;
        }
#pragma unroll
        for (int e = 0; e < 4; e++) {
            int idx = tid + e * 256;
            int r = idx >> 4, kk = idx & 15;
            int m = kb + kk;
            Bs[kk][r] = (m < 283) ? x[(rbase + r) * 283 + m] : 0.f;
        }
        __syncthreads();
#pragma unroll
        for (int kk = 0; kk < 16; kk++) {
            float a0 = As[kk][ty * 4 + 0];
            float a1 = As[kk][ty * 4 + 1];
            float a2 = As[kk][ty * 4 + 2];
            float a3 = As[kk][ty * 4 + 3];
            float4 b = *(const float4*)&Bs[kk][tx * 4];
            acc[0][0] = fmaf(a0, b.x, acc[0][0]); acc[0][1] = fmaf(a0, b.y, acc[0][1]);
            acc[0][2] = fmaf(a0, b.z, acc[0][2]); acc[0][3] = fmaf(a0, b.w, acc[0][3]);
            acc[1][0] = fmaf(a1, b.x, acc[1][0]); acc[1][1] = fmaf(a1, b.y, acc[1][1]);
            acc[1][2] = fmaf(a1, b.z, acc[1][2]); acc[1][3] = fmaf(a1, b.w, acc[1][3]);
            acc[2][0] = fmaf(a2, b.x, acc[2][0]); acc[2][1] = fmaf(a2, b.y, acc[2][1]);
            acc[2][2] = fmaf(a2, b.z, acc[2][2]); acc[2][3] = fmaf(a2, b.w, acc[2][3]);
            acc[3][0] = fmaf(a3, b.x, acc[3][0]); acc[3][1] = fmaf(a3, b.y, acc[3][1]);
            acc[3][2] = fmaf(a3, b.z, acc[3][2]); acc[3][3] = fmaf(a3, b.w, acc[3][3]);
        }
        __syncthreads();
    }

    const int n  = rbase >> 9;            // 64 | 512 -> whole tile in one chunk
    const int l0 = (rbase & 511) + tx * 4;
#pragma unroll
    for (int i = 0; i < 4; i++) {
        float4 v = make_float4(acc[i][0], acc[i][1], acc[i][2], acc[i][3]);
        *(float4*)&g_bufA[(n * HID + cbase + ty * 4 + i) * LC + l0] = v;
    }
}

// ---------------------------------------------------------------------------
// Dilated conv layer as GEMM: out[co][l] = gelu(c)+c,
//   c = bias[co] + sum_{ci,k} W[co][ci][k] * In[ci][l+(k-1)*d]
// M=256 (co) x N=512 (l) x K=768 (ci*3+k), per chunk n.
// Tile 128(co) x 64(l), Ktile=24 (8 ci x 3 taps), 256 threads, 8x4 per thread.
// ---------------------------------------------------------------------------
template <bool A2B>
__global__ __launch_bounds__(256) void conv_kernel(const float* __restrict__ w,
                                                   const float* __restrict__ bias,
                                                   int d) {
    const float* __restrict__ in = A2B ? g_bufA : g_bufB;
    float* __restrict__ out      = A2B ? g_bufB : g_bufA;

    __shared__ float As[24][132];  // [kk][co], 132: aligned float4 rows + spread store banks
    __shared__ float Bs[24][64];   // [kk][ll]

    const int n      = blockIdx.z;
    const int cobase = blockIdx.y * 128;
    const int lbase  = blockIdx.x * 64;
    const int tid = threadIdx.x;
    const int tx = tid & 15, ty = tid >> 4;
    const float* inN = in + n * PLANE;

    float acc[8][4];
#pragma unroll
    for (int i = 0; i < 8; i++)
#pragma unroll
        for (int j = 0; j < 4; j++) acc[i][j] = 0.f;

    for (int kb = 0; kb < 768; kb += 24) {
        // A tile: 128 co x 24 kk straight from W (row-major [co][ci*3+k])
#pragma unroll
        for (int e = 0; e < 12; e++) {
            int idx = tid + e * 256;
            int co = idx / 24, kk = idx - co * 24;
            As[kk][co] = w[(cobase + co) * 768 + kb + kk];
        }
        // B tile: 24 kk x 64 l, shifted gather with zero padding
#pragma unroll
        for (int e = 0; e < 6; e++) {
            int idx = tid + e * 256;
            int kk = idx >> 6, ll = idx & 63;
            int kg = kb + kk;
            int ci = kg / 3;
            int kt = kg - ci * 3;
            int ls = lbase + ll + (kt - 1) * d;
            Bs[kk][ll] = ((unsigned)ls < (unsigned)LC) ? inN[ci * LC + ls] : 0.f;
        }
        __syncthreads();
#pragma unroll
        for (int kk = 0; kk < 24; kk++) {
            float4 a0 = *(const float4*)&As[kk][ty * 8];
            float4 a1 = *(const float4*)&As[kk][ty * 8 + 4];
            float4 b  = *(const float4*)&Bs[kk][tx * 4];
            float av[8] = {a0.x, a0.y, a0.z, a0.w, a1.x, a1.y, a1.z, a1.w};
            float bv[4] = {b.x, b.y, b.z, b.w};
#pragma unroll
            for (int i = 0; i < 8; i++)
#pragma unroll
                for (int j = 0; j < 4; j++)
                    acc[i][j] = fmaf(av[i], bv[j], acc[i][j]);
        }
        __syncthreads();
    }

#pragma unroll
    for (int i = 0; i < 8; i++) {
        int co = cobase + ty * 8 + i;
        float bb = bias[co];
        float4 v;
        v.x = gelu_res(acc[i][0] + bb);
        v.y = gelu_res(acc[i][1] + bb);
        v.z = gelu_res(acc[i][2] + bb);
        v.w = gelu_res(acc[i][3] + bb);
        *(float4*)&out[(n * HID + co) * LC + lbase + tx * 4] = v;
    }
}

// ---------------------------------------------------------------------------
// Head: profile conv (K=20, pad (9,10)) + mean pool + atpm, fused.
// One block per chunk n, 512 threads (one per l).
// Reads final activations from g_bufB.
// ---------------------------------------------------------------------------
__global__ __launch_bounds__(512) void head_kernel(const float* __restrict__ wprof,
                                                   const float* __restrict__ bprof,
                                                   const float* __restrict__ watpm,
                                                   const float* __restrict__ batpm,
                                                   const int* __restrict__ np_raw,
                                                   float* __restrict__ out) {
    __shared__ float buf[544];       // 9 zeros | 512 data | >=10 zeros
    __shared__ float wp[HID * 20];
    __shared__ float wa[HID];
    __shared__ float red[16];

    const int n = blockIdx.x;
    const int tid = threadIdx.x;
    const float* h = g_bufB + n * PLANE;

    for (int i = tid; i < HID * 20; i += 512) wp[i] = wprof[i];
    if (tid < HID) wa[tid] = watpm[tid];
    if (tid < 9)  buf[tid] = 0.f;
    if (tid < 13) buf[521 + tid] = 0.f;

    float accp = 0.f, acca = 0.f;
    __syncthreads();

    for (int c = 0; c < HID; c++) {
        buf[9 + tid] = h[c * LC + tid];
        __syncthreads();
        acca = fmaf(buf[9 + tid], wa[c], acca);
        const float* wr = &wp[c * 20];
#pragma unroll
        for (int k = 0; k < 20; k++)
            accp = fmaf(buf[tid + k], wr[k], accp);
        __syncthreads();
    }

    // profile output
    out[256 + n * LC + tid] = accp + bprof[0];

    // block reduce for atpm
#pragma unroll
    for (int o = 16; o > 0; o >>= 1) acca += __shfl_xor_sync(0xffffffffu, acca, o);
    if ((tid & 31) == 0) red[tid >> 5] = acca;
    __syncthreads();
    if (tid < 16) {
        float v = red[tid];
#pragma unroll
        for (int o = 8; o > 0; o >>= 1) v += __shfl_xor_sync(0x0000ffffu, v, o);
        if (tid == 0) {
            // n_peaks may be int32 or int64 depending on JAX x64 config.
            // int64 LE: words [v0, 0, v1, 0]; int32: [v0, v1].
            int n0 = np_raw[0];
            int n1;
            int w1 = np_raw[1];
            if (w1 != 0) {
                n1 = w1;                              // int32 layout
            } else {
                int w2 = np_raw[2], w3 = np_raw[3];   // int64 layout probe
                n1 = (w2 >= 0 && w2 < 128 && w3 == 0) ? w2 : 0;
            }
            float atpm = v * (1.0f / 512.0f) + batpm[0];
            int p = n & 127, b = n >> 7;
            int lim = (b == 0) ? n0 : n1;
            out[n] = (p < lim) ? atpm : 0.f;
        }
    }
}

// ---------------------------------------------------------------------------
extern "C" void kernel_launch(void* const* d_in, const int* in_sizes, int n_in,
                              void* d_out, int out_size) {
    const float* x       = (const float*)d_in[0];  // (2, 65536, 283)
    const float* w_proj  = (const float*)d_in[1];  // (256, 283)
    const float* tower_w = (const float*)d_in[2];  // (7, 256, 256, 3)
    const float* tower_b = (const float*)d_in[3];  // (7, 256)
    const float* w_prof  = (const float*)d_in[4];  // (1, 256, 20)
    const float* b_prof  = (const float*)d_in[5];  // (1,)
    const float* w_atpm  = (const float*)d_in[6];  // (1, 256, 1)
    const float* b_atpm  = (const float*)d_in[7];  // (1,)
    const int*   n_peaks = (const int*)d_in[8];    // (2,) int32 or int64
    float* out = (float*)d_out;                    // 256 atpms + 131072 profile

    (void)in_sizes; (void)n_in; (void)out_size;

    // 1) projection -> g_bufA
    dim3 gp(131072 / 64, 256 / 64);
    proj_kernel<<<gp, 256>>>(x, w_proj);

    // 2) dilated conv tower, ping-pong A<->B; 7 layers ends in g_bufB
    dim3 gc(LC / 64, HID / 128, NCH);
    for (int i = 0; i < 7; i++) {
        int dil = 2 << i;  // 2,4,8,...,128
        const float* wl = tower_w + (size_t)i * HID * HID * 3;
        const float* bl = tower_b + (size_t)i * HID;
        if ((i & 1) == 0) conv_kernel<true ><<<gc, 256>>>(wl, bl, dil);
        else              conv_kernel<false><<<gc, 256>>>(wl, bl, dil);
    }

    // 3) fused heads from g_bufB
    head_kernel<<<NCH, 512>>>(w_prof, b_prof, w_atpm, b_atpm, n_peaks, out);
}

// round 3
// speedup vs baseline: 1.0733x; 1.0733x over previous
#include <cuda_runtime.h>
#include <cuda_fp16.h>
#include <cstdint>

#define HID 256
#define LC 512
#define NCH 256
#define PLANE (HID*LC)

// Activation ping-pong buffers. Interpreted as fp32 (proj input / final out)
// or as packed (hi,lo) half2 per element for intermediate layers.
__device__ float g_bufA[(size_t)NCH * PLANE];
__device__ float g_bufB[(size_t)NCH * PLANE];

// Fragment-layout weights: [layer][kt][mtile][lane] -> uint4 (8 halves, mma A-frag order)
__device__ uint4 WC_hi[7 * 48 * 16 * 32];
__device__ uint4 WC_lo[7 * 48 * 16 * 32];
__device__ uint4 WP_hi[18 * 16 * 32];
__device__ uint4 WP_lo[18 * 16 * 32];

// ---------------------------------------------------------------------------
__device__ __forceinline__ uint32_t smem_u32(const void* p) {
    uint32_t a;
    asm("{ .reg .u64 t; cvta.to.shared.u64 t, %1; cvt.u32.u64 %0, t; }" : "=r"(a) : "l"(p));
    return a;
}
__device__ __forceinline__ float gelu_res(float c) {
    return fmaf(0.5f * c, 1.0f + erff(c * 0.70710678118654752440f), c);
}
__device__ __forceinline__ uint32_t pack_hl(float v) {
    __half hh = __float2half_rn(v);
    float res = v - __half2float(hh);
    return (uint32_t)__half_as_ushort(hh) |
           ((uint32_t)__half_as_ushort(__float2half_rn(res)) << 16);
}
__device__ __forceinline__ void mma16816(float* d, const uint4 a, uint32_t b0, uint32_t b1) {
    asm volatile(
        "mma.sync.aligned.m16n8k16.row.col.f32.f16.f16.f32 "
        "{%0,%1,%2,%3}, {%4,%5,%6,%7}, {%8,%9}, {%0,%1,%2,%3};"
        : "+f"(d[0]), "+f"(d[1]), "+f"(d[2]), "+f"(d[3])
        : "r"(a.x), "r"(a.y), "r"(a.z), "r"(a.w), "r"(b0), "r"(b1));
}
__device__ __forceinline__ void ldmx4(uint32_t& r0, uint32_t& r1, uint32_t& r2, uint32_t& r3,
                                      uint32_t addr) {
    asm volatile("ldmatrix.sync.aligned.m8n8.x4.shared.b16 {%0,%1,%2,%3}, [%4];"
                 : "=r"(r0), "=r"(r1), "=r"(r2), "=r"(r3) : "r"(addr));
}

// ---------------------------------------------------------------------------
// Weight prep: fp32 -> (hi,lo) fp16 in mma A-fragment order.
// Fragment element order per lane (g=lane>>2, t=lane&3), 4 b32:
//   [(g,2t),(g,2t+1)] [(g+8,2t),(g+8,2t+1)] [(g,2t+8),(g,2t+9)] [(g+8,2t+8),(g+8,2t+9)]
// ---------------------------------------------------------------------------
__device__ __forceinline__ void split_pack(const float* v, uint4& hi, uint4& lo) {
    uint32_t hx[4], lx[4];
#pragma unroll
    for (int q = 0; q < 4; q++) {
        float a = v[2 * q], b = v[2 * q + 1];
        __half ah = __float2half_rn(a), bh = __float2half_rn(b);
        float ar = a - __half2float(ah), br = b - __half2float(bh);
        hx[q] = (uint32_t)__half_as_ushort(ah) | ((uint32_t)__half_as_ushort(bh) << 16);
        lx[q] = (uint32_t)__half_as_ushort(__float2half_rn(ar)) |
                ((uint32_t)__half_as_ushort(__float2half_rn(br)) << 16);
    }
    hi = make_uint4(hx[0], hx[1], hx[2], hx[3]);
    lo = make_uint4(lx[0], lx[1], lx[2], lx[3]);
}

__global__ void prep_conv_w(const float* __restrict__ tw) {
    int idx = blockIdx.x * 256 + threadIdx.x;
    if (idx >= 7 * 48 * 16 * 32) return;
    int lane = idx & 31;
    int mt = (idx >> 5) & 15;
    int kt = (idx >> 9) % 48;
    int layer = (idx >> 9) / 48;
    int g = lane >> 2, t = lane & 3;
    const float* W = tw + (size_t)layer * 256 * 768;
    int r0 = mt * 16 + g, r1 = r0 + 8;
    int c0 = kt * 16 + 2 * t;
    float v[8];
    v[0] = W[r0 * 768 + c0];     v[1] = W[r0 * 768 + c0 + 1];
    v[2] = W[r1 * 768 + c0];     v[3] = W[r1 * 768 + c0 + 1];
    v[4] = W[r0 * 768 + c0 + 8]; v[5] = W[r0 * 768 + c0 + 9];
    v[6] = W[r1 * 768 + c0 + 8]; v[7] = W[r1 * 768 + c0 + 9];
    split_pack(v, WC_hi[idx], WC_lo[idx]);
}

__global__ void prep_proj_w(const float* __restrict__ wp) {
    int idx = blockIdx.x * 256 + threadIdx.x;
    if (idx >= 18 * 16 * 32) return;
    int lane = idx & 31;
    int mt = (idx >> 5) & 15;
    int kt = idx >> 9;
    int g = lane >> 2, t = lane & 3;
    int r0 = mt * 16 + g, r1 = r0 + 8;
    int c0 = kt * 16 + 2 * t;
    float v[8];
    const int cs[4] = {c0, c0 + 1, c0 + 8, c0 + 9};
    const int rs[2] = {r0, r1};
#pragma unroll
    for (int q = 0; q < 4; q++) {
        int cc = cs[q >> 1 ? q : q];  // placeholder to keep indices explicit below
        (void)cc;
    }
    v[0] = (cs[0] < 283) ? wp[rs[0] * 283 + cs[0]] : 0.f;
    v[1] = (cs[1] < 283) ? wp[rs[0] * 283 + cs[1]] : 0.f;
    v[2] = (cs[0] < 283) ? wp[rs[1] * 283 + cs[0]] : 0.f;
    v[3] = (cs[1] < 283) ? wp[rs[1] * 283 + cs[1]] : 0.f;
    v[4] = (cs[2] < 283) ? wp[rs[0] * 283 + cs[2]] : 0.f;
    v[5] = (cs[3] < 283) ? wp[rs[0] * 283 + cs[3]] : 0.f;
    v[6] = (cs[2] < 283) ? wp[rs[1] * 283 + cs[2]] : 0.f;
    v[7] = (cs[3] < 283) ? wp[rs[1] * 283 + cs[3]] : 0.f;
    split_pack(v, WP_hi[idx], WP_lo[idx]);
}

// ---------------------------------------------------------------------------
// Unified mma.sync GEMM kernel, fp16x3 split (fp32-grade).
// MODE 0: proj   C[256co][131072r] = Wp * X^T   (in fp32 x, out half2 hi/lo)
// MODE 1: conv   (in half2, out half2), gelu+res epilogue
// MODE 2: conv last (in half2, out fp32), gelu+res epilogue
// CTA tile 128(M=co) x 128(N=l), warps 2x4 (64x32 each), K-tile 16.
// ---------------------------------------------------------------------------
template <int MODE, bool A2B>
__global__ __launch_bounds__(256, 1) void gemm_kernel(
    const float* __restrict__ xin, const float* __restrict__ bias,
    int dil, int layer)
{
    constexpr int KT = (MODE == 0) ? 18 : 48;
    __shared__ unsigned short Bs[2][2][128 * 24];   // [stage][hi/lo][l*24+k]

    const int tid = threadIdx.x;
    const int lane = tid & 31;
    const int wid = tid >> 5;
    const int wm = wid >> 2;      // 0..1
    const int wn = wid & 3;       // 0..3
    const int mbase = blockIdx.y * 128;

    const uint4* __restrict__ WAhi =
        (MODE == 0) ? WP_hi : (WC_hi + (size_t)layer * 48 * 16 * 32);
    const uint4* __restrict__ WAlo =
        (MODE == 0) ? WP_lo : (WC_lo + (size_t)layer * 48 * 16 * 32);

    const uint32_t* inw = nullptr;
    int n = 0, l0 = 0, rbase = 0;
    if (MODE == 0) {
        rbase = blockIdx.x * 128;
    } else {
        n = blockIdx.z;
        l0 = blockIdx.x * 128;
        inw = (const uint32_t*)(A2B ? g_bufA : g_bufB) + (size_t)n * PLANE;
    }

    const int kk = tid & 15;
    const int lrow = tid >> 4;

    uint32_t vr[8];

    auto gather = [&](int kt) {
        if (MODE == 0) {
            int m = kt * 16 + kk;
#pragma unroll
            for (int e = 0; e < 8; e++) {
                float v = 0.f;
                if (m < 283) v = xin[(size_t)(rbase + lrow + e * 16) * 283 + m];
                vr[e] = pack_hl(v);
            }
        } else {
            int kg = kt * 16 + kk;
            int ci = kg / 3;
            int sh = (kg - 3 * ci - 1) * dil;
#pragma unroll
            for (int e = 0; e < 8; e++) {
                int ls = l0 + lrow + e * 16 + sh;
                vr[e] = ((unsigned)ls < 512u) ? inw[ci * 512 + ls] : 0u;
            }
        }
    };
    auto stsB = [&](int s) {
#pragma unroll
        for (int e = 0; e < 8; e++) {
            int l = lrow + e * 16;
            Bs[s][0][l * 24 + kk] = (unsigned short)(vr[e] & 0xffff);
            Bs[s][1][l * 24 + kk] = (unsigned short)(vr[e] >> 16);
        }
    };

    uint4 Ah[2][4], Al[2][4];
    auto loadA = [&](int kt, int b) {
#pragma unroll
        for (int i = 0; i < 4; i++) {
            int mt = blockIdx.y * 8 + wm * 4 + i;
            size_t o = (size_t)(kt * 16 + mt) * 32 + lane;
            Ah[b][i] = WAhi[o];
            Al[b][i] = WAlo[o];
        }
    };

    float acc[4][4][4];
#pragma unroll
    for (int i = 0; i < 4; i++)
#pragma unroll
        for (int j = 0; j < 4; j++)
#pragma unroll
            for (int q = 0; q < 4; q++) acc[i][j][q] = 0.f;

    gather(0); stsB(0); loadA(0, 0);
    __syncthreads();

    const uint32_t sbase = smem_u32(Bs);
    const int rsel = (lane & 7) + ((lane & 16) ? 8 : 0);
    const int csel = (lane & 8) ? 8 : 0;

    auto body = [&](int kt, int s) {
        if (kt + 1 < KT) { gather(kt + 1); loadA(kt + 1, s ^ 1); }

        uint32_t bh[4][2], bl[4][2];
#pragma unroll
        for (int pr = 0; pr < 2; pr++) {
            int row = wn * 32 + pr * 16 + rsel;
            uint32_t ah = sbase + (uint32_t)(((s * 2 + 0) * 3072 + row * 24 + csel) * 2);
            uint32_t al = sbase + (uint32_t)(((s * 2 + 1) * 3072 + row * 24 + csel) * 2);
            uint32_t r0, r1, r2, r3;
            ldmx4(r0, r1, r2, r3, ah);
            bh[pr * 2][0] = r0; bh[pr * 2][1] = r1;
            bh[pr * 2 + 1][0] = r2; bh[pr * 2 + 1][1] = r3;
            ldmx4(r0, r1, r2, r3, al);
            bl[pr * 2][0] = r0; bl[pr * 2][1] = r1;
            bl[pr * 2 + 1][0] = r2; bl[pr * 2 + 1][1] = r3;
        }
#pragma unroll
        for (int i = 0; i < 4; i++)
#pragma unroll
            for (int j = 0; j < 4; j++) {
                mma16816(acc[i][j], Ah[s][i], bh[j][0], bh[j][1]);
                mma16816(acc[i][j], Ah[s][i], bl[j][0], bl[j][1]);
                mma16816(acc[i][j], Al[s][i], bh[j][0], bh[j][1]);
            }
        if (kt + 1 < KT) stsB(s ^ 1);
        __syncthreads();
    };

    for (int kt2 = 0; kt2 < KT; kt2 += 2) {   // KT even; s literal -> regs
        body(kt2, 0);
        body(kt2 + 1, 1);
    }

    // ---- epilogue ----
    const int g = lane >> 2, t4 = lane & 3;
    if (MODE == 0) {
        int nn = rbase >> 9;
        int lp0 = rbase & 511;
        uint32_t* outp = (uint32_t*)g_bufA + (size_t)nn * PLANE;
#pragma unroll
        for (int i = 0; i < 4; i++) {
            int co0 = mbase + wm * 64 + i * 16 + g;
#pragma unroll
            for (int j = 0; j < 4; j++) {
                int lp = lp0 + wn * 32 + j * 8 + 2 * t4;
                uint2 v0, v1;
                v0.x = pack_hl(acc[i][j][0]); v0.y = pack_hl(acc[i][j][1]);
                v1.x = pack_hl(acc[i][j][2]); v1.y = pack_hl(acc[i][j][3]);
                *(uint2*)&outp[(size_t)co0 * 512 + lp] = v0;
                *(uint2*)&outp[(size_t)(co0 + 8) * 512 + lp] = v1;
            }
        }
    } else if (MODE == 1) {
        uint32_t* outp = (uint32_t*)(A2B ? g_bufB : g_bufA) + (size_t)n * PLANE;
#pragma unroll
        for (int i = 0; i < 4; i++) {
            int co0 = mbase + wm * 64 + i * 16 + g;
            float b0 = bias[co0], b1 = bias[co0 + 8];
#pragma unroll
            for (int j = 0; j < 4; j++) {
                int lp = l0 + wn * 32 + j * 8 + 2 * t4;
                uint2 v0, v1;
                v0.x = pack_hl(gelu_res(acc[i][j][0] + b0));
                v0.y = pack_hl(gelu_res(acc[i][j][1] + b0));
                v1.x = pack_hl(gelu_res(acc[i][j][2] + b1));
                v1.y = pack_hl(gelu_res(acc[i][j][3] + b1));
                *(uint2*)&outp[(size_t)co0 * 512 + lp] = v0;
                *(uint2*)&outp[(size_t)(co0 + 8) * 512 + lp] = v1;
            }
        }
    } else {
        float* outp = (A2B ? g_bufB : g_bufA) + (size_t)n * PLANE;
#pragma unroll
        for (int i = 0; i < 4; i++) {
            int co0 = mbase + wm * 64 + i * 16 + g;
            float b0 = bias[co0], b1 = bias[co0 + 8];
#pragma unroll
            for (int j = 0; j < 4; j++) {
                int lp = l0 + wn * 32 + j * 8 + 2 * t4;
                float2 v0, v1;
                v0.x = gelu_res(acc[i][j][0] + b0);
                v0.y = gelu_res(acc[i][j][1] + b0);
                v1.x = gelu_res(acc[i][j][2] + b1);
                v1.y = gelu_res(acc[i][j][3] + b1);
                *(float2*)&outp[(size_t)co0 * 512 + lp] = v0;
                *(float2*)&outp[(size_t)(co0 + 8) * 512 + lp] = v1;
            }
        }
    }
}

// ---------------------------------------------------------------------------
// Head: profile conv (K=20, pad (9,10)) + mean pool + atpm, fused.
// ---------------------------------------------------------------------------
__global__ __launch_bounds__(512) void head_kernel(const float* __restrict__ wprof,
                                                   const float* __restrict__ bprof,
                                                   const float* __restrict__ watpm,
                                                   const float* __restrict__ batpm,
                                                   const int* __restrict__ np_raw,
                                                   float* __restrict__ out) {
    __shared__ float buf[544];
    __shared__ float wp[HID * 20];
    __shared__ float wa[HID];
    __shared__ float red[16];

    const int n = blockIdx.x;
    const int tid = threadIdx.x;
    const float* h = g_bufB + (size_t)n * PLANE;

    for (int i = tid; i < HID * 20; i += 512) wp[i] = wprof[i];
    if (tid < HID) wa[tid] = watpm[tid];
    if (tid < 9)  buf[tid] = 0.f;
    if (tid < 13) buf[521 + tid] = 0.f;

    float accp = 0.f, acca = 0.f;
    __syncthreads();

    for (int c = 0; c < HID; c++) {
        buf[9 + tid] = h[c * LC + tid];
        __syncthreads();
        acca = fmaf(buf[9 + tid], wa[c], acca);
        const float* wr = &wp[c * 20];
#pragma unroll
        for (int k = 0; k < 20; k++)
            accp = fmaf(buf[tid + k], wr[k], accp);
        __syncthreads();
    }

    out[256 + n * LC + tid] = accp + bprof[0];

#pragma unroll
    for (int o = 16; o > 0; o >>= 1) acca += __shfl_xor_sync(0xffffffffu, acca, o);
    if ((tid & 31) == 0) red[tid >> 5] = acca;
    __syncthreads();
    if (tid < 16) {
        float v = red[tid];
#pragma unroll
        for (int o = 8; o > 0; o >>= 1) v += __shfl_xor_sync(0x0000ffffu, v, o);
        if (tid == 0) {
            int n0 = np_raw[0];
            int n1;
            int w1 = np_raw[1];
            if (w1 != 0) {
                n1 = w1;
            } else {
                int w2 = np_raw[2], w3 = np_raw[3];
                n1 = (w2 >= 0 && w2 < 128 && w3 == 0) ? w2 : 0;
            }
            float atpm = v * (1.0f / 512.0f) + batpm[0];
            int p = n & 127, b = n >> 7;
            int lim = (b == 0) ? n0 : n1;
            out[n] = (p < lim) ? atpm : 0.f;
        }
    }
}

// ---------------------------------------------------------------------------
extern "C" void kernel_launch(void* const* d_in, const int* in_sizes, int n_in,
                              void* d_out, int out_size) {
    const float* x       = (const float*)d_in[0];
    const float* w_proj  = (const float*)d_in[1];
    const float* tower_w = (const float*)d_in[2];
    const float* tower_b = (const float*)d_in[3];
    const float* w_prof  = (const float*)d_in[4];
    const float* b_prof  = (const float*)d_in[5];
    const float* w_atpm  = (const float*)d_in[6];
    const float* b_atpm  = (const float*)d_in[7];
    const int*   n_peaks = (const int*)d_in[8];
    float* out = (float*)d_out;

    (void)in_sizes; (void)n_in; (void)out_size;

    // 0) weight prep (fragment layout + fp16 hi/lo split)
    prep_conv_w<<<672, 256>>>(tower_w);
    prep_proj_w<<<36, 256>>>(w_proj);

    // 1) projection -> g_bufA (half2 hi/lo)
    gemm_kernel<0, true><<<dim3(1024, 2, 1), 256>>>(x, nullptr, 0, 0);

    // 2) conv tower, ping-pong; layer 6 writes fp32 into g_bufB
    dim3 gc(4, 2, NCH);
    for (int i = 0; i < 7; i++) {
        int dil = 2 << i;
        const float* bl = tower_b + (size_t)i * HID;
        if (i == 6)           gemm_kernel<2, true ><<<gc, 256>>>(nullptr, bl, dil, i);
        else if ((i & 1) == 0) gemm_kernel<1, true ><<<gc, 256>>>(nullptr, bl, dil, i);
        else                   gemm_kernel<1, false><<<gc, 256>>>(nullptr, bl, dil, i);
    }

    // 3) fused heads from g_bufB
    head_kernel<<<NCH, 512>>>(w_prof, b_prof, w_atpm, b_atpm, n_peaks, out);
}

// round 4
// speedup vs baseline: 2.6075x; 2.4294x over previous
#include <cuda_runtime.h>
#include <cuda_fp16.h>
#include <cstdint>

#define HID 256
#define LC 512
#define NCH 256
#define PLANE (HID*LC)

// Activation ping-pong buffers: packed (hi,lo) half2 per element, or fp32 at the ends.
__device__ float g_bufA[(size_t)NCH * PLANE];
__device__ float g_bufB[(size_t)NCH * PLANE];

// Fragment-layout weights: [layer][kt][mtile][lane] -> uint4 (8 halves, mma A-frag order)
__device__ uint4 WC_hi[7 * 48 * 16 * 32];
__device__ uint4 WC_lo[7 * 48 * 16 * 32];
__device__ uint4 WP_hi[18 * 16 * 32];
__device__ uint4 WP_lo[18 * 16 * 32];

// ---------------------------------------------------------------------------
__device__ __forceinline__ uint32_t smem_u32(const void* p) {
    uint32_t a;
    asm("{ .reg .u64 t; cvta.to.shared.u64 t, %1; cvt.u32.u64 %0, t; }" : "=r"(a) : "l"(p));
    return a;
}
__device__ __forceinline__ float gelu_res(float c) {
    return fmaf(0.5f * c, 1.0f + erff(c * 0.70710678118654752440f), c);
}
__device__ __forceinline__ uint32_t pack_hl(float v) {
    __half hh = __float2half_rn(v);
    float res = v - __half2float(hh);
    return (uint32_t)__half_as_ushort(hh) |
           ((uint32_t)__half_as_ushort(__float2half_rn(res)) << 16);
}
__device__ __forceinline__ void mma16816(float* d, const uint4 a, uint32_t b0, uint32_t b1) {
    asm volatile(
        "mma.sync.aligned.m16n8k16.row.col.f32.f16.f16.f32 "
        "{%0,%1,%2,%3}, {%4,%5,%6,%7}, {%8,%9}, {%0,%1,%2,%3};"
        : "+f"(d[0]), "+f"(d[1]), "+f"(d[2]), "+f"(d[3])
        : "r"(a.x), "r"(a.y), "r"(a.z), "r"(a.w), "r"(b0), "r"(b1));
}
__device__ __forceinline__ void ldmx4(uint32_t& r0, uint32_t& r1, uint32_t& r2, uint32_t& r3,
                                      uint32_t addr) {
    asm volatile("ldmatrix.sync.aligned.m8n8.x4.shared.b16 {%0,%1,%2,%3}, [%4];"
                 : "=r"(r0), "=r"(r1), "=r"(r2), "=r"(r3) : "r"(addr));
}
__device__ __forceinline__ void ldmx4t(uint32_t& r0, uint32_t& r1, uint32_t& r2, uint32_t& r3,
                                       uint32_t addr) {
    asm volatile("ldmatrix.sync.aligned.m8n8.x4.trans.shared.b16 {%0,%1,%2,%3}, [%4];"
                 : "=r"(r0), "=r"(r1), "=r"(r2), "=r"(r3) : "r"(addr));
}

// ---------------------------------------------------------------------------
// Weight prep: fp32 -> (hi,lo) fp16 in mma A-fragment order.
// ---------------------------------------------------------------------------
__device__ __forceinline__ void split_pack(const float* v, uint4& hi, uint4& lo) {
    uint32_t hx[4], lx[4];
#pragma unroll
    for (int q = 0; q < 4; q++) {
        float a = v[2 * q], b = v[2 * q + 1];
        __half ah = __float2half_rn(a), bh = __float2half_rn(b);
        float ar = a - __half2float(ah), br = b - __half2float(bh);
        hx[q] = (uint32_t)__half_as_ushort(ah) | ((uint32_t)__half_as_ushort(bh) << 16);
        lx[q] = (uint32_t)__half_as_ushort(__float2half_rn(ar)) |
                ((uint32_t)__half_as_ushort(__float2half_rn(br)) << 16);
    }
    hi = make_uint4(hx[0], hx[1], hx[2], hx[3]);
    lo = make_uint4(lx[0], lx[1], lx[2], lx[3]);
}

__global__ void prep_conv_w(const float* __restrict__ tw) {
    int idx = blockIdx.x * 256 + threadIdx.x;
    if (idx >= 7 * 48 * 16 * 32) return;
    int lane = idx & 31;
    int mt = (idx >> 5) & 15;
    int kt = (idx >> 9) % 48;
    int layer = (idx >> 9) / 48;
    int g = lane >> 2, t = lane & 3;
    const float* W = tw + (size_t)layer * 256 * 768;
    int r0 = mt * 16 + g, r1 = r0 + 8;
    int c0 = kt * 16 + 2 * t;
    float v[8];
    v[0] = W[r0 * 768 + c0];     v[1] = W[r0 * 768 + c0 + 1];
    v[2] = W[r1 * 768 + c0];     v[3] = W[r1 * 768 + c0 + 1];
    v[4] = W[r0 * 768 + c0 + 8]; v[5] = W[r0 * 768 + c0 + 9];
    v[6] = W[r1 * 768 + c0 + 8]; v[7] = W[r1 * 768 + c0 + 9];
    split_pack(v, WC_hi[idx], WC_lo[idx]);
}

__global__ void prep_proj_w(const float* __restrict__ wp) {
    int idx = blockIdx.x * 256 + threadIdx.x;
    if (idx >= 18 * 16 * 32) return;
    int lane = idx & 31;
    int mt = (idx >> 5) & 15;
    int kt = idx >> 9;
    int g = lane >> 2, t = lane & 3;
    int r0 = mt * 16 + g, r1 = r0 + 8;
    int c0 = kt * 16 + 2 * t;
    const int cs[4] = {c0, c0 + 1, c0 + 8, c0 + 9};
    float v[8];
    v[0] = (cs[0] < 283) ? wp[r0 * 283 + cs[0]] : 0.f;
    v[1] = (cs[1] < 283) ? wp[r0 * 283 + cs[1]] : 0.f;
    v[2] = (cs[0] < 283) ? wp[r1 * 283 + cs[0]] : 0.f;
    v[3] = (cs[1] < 283) ? wp[r1 * 283 + cs[1]] : 0.f;
    v[4] = (cs[2] < 283) ? wp[r0 * 283 + cs[2]] : 0.f;
    v[5] = (cs[3] < 283) ? wp[r0 * 283 + cs[3]] : 0.f;
    v[6] = (cs[2] < 283) ? wp[r1 * 283 + cs[2]] : 0.f;
    v[7] = (cs[3] < 283) ? wp[r1 * 283 + cs[3]] : 0.f;
    split_pack(v, WP_hi[idx], WP_lo[idx]);
}

// ---------------------------------------------------------------------------
// Projection kernel (R3-validated path): C[256co][131072r] = Wp * X^T.
// Writes packed (hi,lo) activations to g_bufA. [l][k] smem + non-trans ldmatrix.
// ---------------------------------------------------------------------------
__global__ __launch_bounds__(256, 1) void proj_kernel(const float* __restrict__ xin) {
    constexpr int KT = 18;
    __shared__ unsigned short Bs[2][2][128 * 24];

    const int tid = threadIdx.x;
    const int lane = tid & 31;
    const int wid = tid >> 5;
    const int wm = wid >> 2;
    const int wn = wid & 3;
    const int mbase = blockIdx.y * 128;
    const int rbase = blockIdx.x * 128;

    const int kk = tid & 15;
    const int lrow = tid >> 4;
    uint32_t vr[8];

    auto gather = [&](int kt) {
        int m = kt * 16 + kk;
#pragma unroll
        for (int e = 0; e < 8; e++) {
            float v = 0.f;
            if (m < 283) v = xin[(size_t)(rbase + lrow + e * 16) * 283 + m];
            vr[e] = pack_hl(v);
        }
    };
    auto stsB = [&](int s) {
#pragma unroll
        for (int e = 0; e < 8; e++) {
            int l = lrow + e * 16;
            Bs[s][0][l * 24 + kk] = (unsigned short)(vr[e] & 0xffff);
            Bs[s][1][l * 24 + kk] = (unsigned short)(vr[e] >> 16);
        }
    };

    uint4 Ah[2][4], Al[2][4];
    auto loadA = [&](int kt, int b) {
#pragma unroll
        for (int i = 0; i < 4; i++) {
            int mt = blockIdx.y * 8 + wm * 4 + i;
            size_t o = (size_t)(kt * 16 + mt) * 32 + lane;
            Ah[b][i] = WP_hi[o];
            Al[b][i] = WP_lo[o];
        }
    };

    float acc[4][4][4];
#pragma unroll
    for (int i = 0; i < 4; i++)
#pragma unroll
        for (int j = 0; j < 4; j++)
#pragma unroll
            for (int q = 0; q < 4; q++) acc[i][j][q] = 0.f;

    gather(0); stsB(0); loadA(0, 0);
    __syncthreads();

    const uint32_t sbase = smem_u32(Bs);
    const int rsel = (lane & 7) + ((lane & 16) ? 8 : 0);
    const int csel = (lane & 8) ? 8 : 0;

    auto body = [&](int kt, int s) {
        if (kt + 1 < KT) { gather(kt + 1); loadA(kt + 1, s ^ 1); }
        uint32_t bh[4][2], bl[4][2];
#pragma unroll
        for (int pr = 0; pr < 2; pr++) {
            int row = wn * 32 + pr * 16 + rsel;
            uint32_t ah = sbase + (uint32_t)(((s * 2 + 0) * 3072 + row * 24 + csel) * 2);
            uint32_t al = sbase + (uint32_t)(((s * 2 + 1) * 3072 + row * 24 + csel) * 2);
            uint32_t r0, r1, r2, r3;
            ldmx4(r0, r1, r2, r3, ah);
            bh[pr * 2][0] = r0; bh[pr * 2][1] = r1;
            bh[pr * 2 + 1][0] = r2; bh[pr * 2 + 1][1] = r3;
            ldmx4(r0, r1, r2, r3, al);
            bl[pr * 2][0] = r0; bl[pr * 2][1] = r1;
            bl[pr * 2 + 1][0] = r2; bl[pr * 2 + 1][1] = r3;
        }
#pragma unroll
        for (int i = 0; i < 4; i++)
#pragma unroll
            for (int j = 0; j < 4; j++) {
                mma16816(acc[i][j], Ah[s][i], bh[j][0], bh[j][1]);
                mma16816(acc[i][j], Ah[s][i], bl[j][0], bl[j][1]);
                mma16816(acc[i][j], Al[s][i], bh[j][0], bh[j][1]);
            }
        if (kt + 1 < KT) stsB(s ^ 1);
        __syncthreads();
    };

    for (int kt2 = 0; kt2 < KT; kt2 += 2) { body(kt2, 0); body(kt2 + 1, 1); }

    const int g = lane >> 2, t4 = lane & 3;
    int nn = rbase >> 9;
    int lp0 = rbase & 511;
    uint32_t* outp = (uint32_t*)g_bufA + (size_t)nn * PLANE;
#pragma unroll
    for (int i = 0; i < 4; i++) {
        int co0 = mbase + wm * 64 + i * 16 + g;
#pragma unroll
        for (int j = 0; j < 4; j++) {
            int lp = lp0 + wn * 32 + j * 8 + 2 * t4;
            uint2 v0, v1;
            v0.x = pack_hl(acc[i][j][0]); v0.y = pack_hl(acc[i][j][1]);
            v1.x = pack_hl(acc[i][j][2]); v1.y = pack_hl(acc[i][j][3]);
            *(uint2*)&outp[(size_t)co0 * 512 + lp] = v0;
            *(uint2*)&outp[(size_t)(co0 + 8) * 512 + lp] = v1;
        }
    }
}

// ---------------------------------------------------------------------------
// Conv layer kernel: coalesced gather, [k][l] smem + ldmatrix.trans, 2 CTAs/SM.
// MODE 1: packed half2 out; MODE 2: fp32 out (last layer). gelu+res epilogue.
// CTA: 256 thr, tile M=128 x N=128, K-tile 16, 48 tiles.
// ---------------------------------------------------------------------------
#define SSTR 136                 // halves per k-row (128 + 8 pad)
#define STAGE_H (16 * SSTR)      // halves per (stage,hi/lo) plane

__device__ __forceinline__ uint2 ld2_guard(const uint32_t* row, int base) {
    if ((unsigned)base <= 510u) return *(const uint2*)(row + base);
    uint2 r;
    r.x = ((unsigned)(base)     < 512u) ? row[base]     : 0u;
    r.y = ((unsigned)(base + 1) < 512u) ? row[base + 1] : 0u;
    return r;
}

template <int MODE, bool A2B>
__global__ __launch_bounds__(256, 2) void conv_kernel(
    const float* __restrict__ bias, int dil, int layer)
{
    constexpr int KT = 48;
    __shared__ unsigned short Bs[2][2][STAGE_H];   // [stage][hi/lo][k*SSTR + l]

    const int tid = threadIdx.x;
    const int lane = tid & 31;
    const int wid = tid >> 5;
    const int wm = wid >> 2;      // 0..1
    const int wn = wid & 3;       // 0..3
    const int mbase = blockIdx.y * 128;
    const int n = blockIdx.z;
    const int l0 = blockIdx.x * 128;

    const uint4* __restrict__ WAhi = WC_hi + (size_t)layer * 48 * 16 * 32;
    const uint4* __restrict__ WAlo = WC_lo + (size_t)layer * 48 * 16 * 32;
    const uint32_t* __restrict__ inw =
        (const uint32_t*)(A2B ? g_bufA : g_bufB) + (size_t)n * PLANE;

    // gather assignment: thread -> (k-row kk, 8 consecutive l at ll0)
    const int kk = tid >> 4;
    const int ll0 = (tid & 15) * 8;

    uint2 v[4];
    auto gather = [&](int kt) {
        int kg = kt * 16 + kk;
        int ci = kg / 3;
        int sh = (kg - 3 * ci - 1) * dil;
        const uint32_t* rowp = inw + ci * 512;
        int base = l0 + ll0 + sh;
        v[0] = ld2_guard(rowp, base);
        v[1] = ld2_guard(rowp, base + 2);
        v[2] = ld2_guard(rowp, base + 4);
        v[3] = ld2_guard(rowp, base + 6);
    };
    auto stsB = [&](int s) {
        uint4 hv, lv;
        hv.x = (v[0].x & 0xffffu) | (v[0].y << 16);
        hv.y = (v[1].x & 0xffffu) | (v[1].y << 16);
        hv.z = (v[2].x & 0xffffu) | (v[2].y << 16);
        hv.w = (v[3].x & 0xffffu) | (v[3].y << 16);
        lv.x = (v[0].x >> 16) | (v[0].y & 0xffff0000u);
        lv.y = (v[1].x >> 16) | (v[1].y & 0xffff0000u);
        lv.z = (v[2].x >> 16) | (v[2].y & 0xffff0000u);
        lv.w = (v[3].x >> 16) | (v[3].y & 0xffff0000u);
        *(uint4*)&Bs[s][0][kk * SSTR + ll0] = hv;
        *(uint4*)&Bs[s][1][kk * SSTR + ll0] = lv;
    };

    float acc[4][4][4];
#pragma unroll
    for (int i = 0; i < 4; i++)
#pragma unroll
        for (int j = 0; j < 4; j++)
#pragma unroll
            for (int q = 0; q < 4; q++) acc[i][j][q] = 0.f;

    gather(0); stsB(0);
    __syncthreads();

    const uint32_t sbase = smem_u32(Bs);
    // ldmatrix.trans lane address: 4 tiles = (k0-7,n0),(k8-15,n0),(k0-7,n0+8),(k8-15,n0+8)
    const int grp = lane >> 3, lwi = lane & 7;
    const int krow = (grp & 1) * 8 + lwi;
    const int ncol = wn * 32 + (grp >> 1) * 8;   // + jj*16 at use

    for (int kt = 0; kt < KT; kt++) {
        const int s = kt & 1;
        if (kt + 1 < KT) gather(kt + 1);

        uint32_t bh[4][2], bl[4][2];
#pragma unroll
        for (int jj = 0; jj < 2; jj++) {
            uint32_t ah = sbase +
                (uint32_t)(((s * 2 + 0) * STAGE_H + krow * SSTR + ncol + jj * 16) * 2);
            uint32_t al = sbase +
                (uint32_t)(((s * 2 + 1) * STAGE_H + krow * SSTR + ncol + jj * 16) * 2);
            uint32_t r0, r1, r2, r3;
            ldmx4t(r0, r1, r2, r3, ah);
            bh[jj * 2][0] = r0;     bh[jj * 2][1] = r1;
            bh[jj * 2 + 1][0] = r2; bh[jj * 2 + 1][1] = r3;
            ldmx4t(r0, r1, r2, r3, al);
            bl[jj * 2][0] = r0;     bl[jj * 2][1] = r1;
            bl[jj * 2 + 1][0] = r2; bl[jj * 2 + 1][1] = r3;
        }
#pragma unroll
        for (int ih = 0; ih < 4; ih += 2) {
            uint4 Ah[2], Al[2];
#pragma unroll
            for (int u = 0; u < 2; u++) {
                int mt = blockIdx.y * 8 + wm * 4 + ih + u;
                size_t o = (size_t)(kt * 16 + mt) * 32 + lane;
                Ah[u] = WAhi[o];
                Al[u] = WAlo[o];
            }
#pragma unroll
            for (int u = 0; u < 2; u++)
#pragma unroll
                for (int j = 0; j < 4; j++) {
                    mma16816(acc[ih + u][j], Ah[u], bh[j][0], bh[j][1]);
                    mma16816(acc[ih + u][j], Ah[u], bl[j][0], bl[j][1]);
                    mma16816(acc[ih + u][j], Al[u], bh[j][0], bh[j][1]);
                }
        }
        if (kt + 1 < KT) stsB(s ^ 1);
        __syncthreads();
    }

    // ---- epilogue ----
    const int g = lane >> 2, t4 = lane & 3;
    if (MODE == 1) {
        uint32_t* outp = (uint32_t*)(A2B ? g_bufB : g_bufA) + (size_t)n * PLANE;
#pragma unroll
        for (int i = 0; i < 4; i++) {
            int co0 = mbase + wm * 64 + i * 16 + g;
            float b0 = bias[co0], b1 = bias[co0 + 8];
#pragma unroll
            for (int j = 0; j < 4; j++) {
                int lp = l0 + wn * 32 + j * 8 + 2 * t4;
                uint2 v0, v1;
                v0.x = pack_hl(gelu_res(acc[i][j][0] + b0));
                v0.y = pack_hl(gelu_res(acc[i][j][1] + b0));
                v1.x = pack_hl(gelu_res(acc[i][j][2] + b1));
                v1.y = pack_hl(gelu_res(acc[i][j][3] + b1));
                *(uint2*)&outp[(size_t)co0 * 512 + lp] = v0;
                *(uint2*)&outp[(size_t)(co0 + 8) * 512 + lp] = v1;
            }
        }
    } else {
        float* outp = (A2B ? g_bufB : g_bufA) + (size_t)n * PLANE;
#pragma unroll
        for (int i = 0; i < 4; i++) {
            int co0 = mbase + wm * 64 + i * 16 + g;
            float b0 = bias[co0], b1 = bias[co0 + 8];
#pragma unroll
            for (int j = 0; j < 4; j++) {
                int lp = l0 + wn * 32 + j * 8 + 2 * t4;
                float2 v0, v1;
                v0.x = gelu_res(acc[i][j][0] + b0);
                v0.y = gelu_res(acc[i][j][1] + b0);
                v1.x = gelu_res(acc[i][j][2] + b1);
                v1.y = gelu_res(acc[i][j][3] + b1);
                *(float2*)&outp[(size_t)co0 * 512 + lp] = v0;
                *(float2*)&outp[(size_t)(co0 + 8) * 512 + lp] = v1;
            }
        }
    }
}

// ---------------------------------------------------------------------------
// Head: profile conv (K=20, pad (9,10)) + mean pool + atpm, fused.
// ---------------------------------------------------------------------------
__global__ __launch_bounds__(512) void head_kernel(const float* __restrict__ wprof,
                                                   const float* __restrict__ bprof,
                                                   const float* __restrict__ watpm,
                                                   const float* __restrict__ batpm,
                                                   const int* __restrict__ np_raw,
                                                   float* __restrict__ out) {
    __shared__ float buf[544];
    __shared__ float wp[HID * 20];
    __shared__ float wa[HID];
    __shared__ float red[16];

    const int n = blockIdx.x;
    const int tid = threadIdx.x;
    const float* h = g_bufB + (size_t)n * PLANE;

    for (int i = tid; i < HID * 20; i += 512) wp[i] = wprof[i];
    if (tid < HID) wa[tid] = watpm[tid];
    if (tid < 9)  buf[tid] = 0.f;
    if (tid < 13) buf[521 + tid] = 0.f;

    float accp = 0.f, acca = 0.f;
    __syncthreads();

    for (int c = 0; c < HID; c++) {
        buf[9 + tid] = h[c * LC + tid];
        __syncthreads();
        acca = fmaf(buf[9 + tid], wa[c], acca);
        const float* wr = &wp[c * 20];
#pragma unroll
        for (int k = 0; k < 20; k++)
            accp = fmaf(buf[tid + k], wr[k], accp);
        __syncthreads();
    }

    out[256 + n * LC + tid] = accp + bprof[0];

#pragma unroll
    for (int o = 16; o > 0; o >>= 1) acca += __shfl_xor_sync(0xffffffffu, acca, o);
    if ((tid & 31) == 0) red[tid >> 5] = acca;
    __syncthreads();
    if (tid < 16) {
        float vv = red[tid];
#pragma unroll
        for (int o = 8; o > 0; o >>= 1) vv += __shfl_xor_sync(0x0000ffffu, vv, o);
        if (tid == 0) {
            int n0 = np_raw[0];
            int n1;
            int w1 = np_raw[1];
            if (w1 != 0) {
                n1 = w1;
            } else {
                int w2 = np_raw[2], w3 = np_raw[3];
                n1 = (w2 >= 0 && w2 < 128 && w3 == 0) ? w2 : 0;
            }
            float atpm = vv * (1.0f / 512.0f) + batpm[0];
            int p = n & 127, b = n >> 7;
            int lim = (b == 0) ? n0 : n1;
            out[n] = (p < lim) ? atpm : 0.f;
        }
    }
}

// ---------------------------------------------------------------------------
extern "C" void kernel_launch(void* const* d_in, const int* in_sizes, int n_in,
                              void* d_out, int out_size) {
    const float* x       = (const float*)d_in[0];
    const float* w_proj  = (const float*)d_in[1];
    const float* tower_w = (const float*)d_in[2];
    const float* tower_b = (const float*)d_in[3];
    const float* w_prof  = (const float*)d_in[4];
    const float* b_prof  = (const float*)d_in[5];
    const float* w_atpm  = (const float*)d_in[6];
    const float* b_atpm  = (const float*)d_in[7];
    const int*   n_peaks = (const int*)d_in[8];
    float* out = (float*)d_out;

    (void)in_sizes; (void)n_in; (void)out_size;

    // 0) weight prep (fragment layout + fp16 hi/lo split)
    prep_conv_w<<<672, 256>>>(tower_w);
    prep_proj_w<<<36, 256>>>(w_proj);

    // 1) projection -> g_bufA (packed half2 hi/lo)
    proj_kernel<<<dim3(1024, 2, 1), 256>>>(x);

    // 2) conv tower, ping-pong; layer 6 writes fp32 into g_bufB
    dim3 gc(4, 2, NCH);
    for (int i = 0; i < 7; i++) {
        int dil = 2 << i;
        const float* bl = tower_b + (size_t)i * HID;
        if (i == 6)            conv_kernel<2, true ><<<gc, 256>>>(bl, dil, i);
        else if ((i & 1) == 0) conv_kernel<1, true ><<<gc, 256>>>(bl, dil, i);
        else                   conv_kernel<1, false><<<gc, 256>>>(bl, dil, i);
    }

    // 3) fused heads from g_bufB
    head_kernel<<<NCH, 512>>>(w_prof, b_prof, w_atpm, b_atpm, n_peaks, out);
}

// round 6
// speedup vs baseline: 2.8837x; 1.1059x over previous
#include <cuda_runtime.h>
#include <cuda_fp16.h>
#include <cstdint>

#define HID 256
#define LC 512
#define NCH 256
#define PLANE (HID*LC)

// Activation ping-pong buffers: packed (hi,lo) half2 per element, or fp32 at the ends.
__device__ float g_bufA[(size_t)NCH * PLANE];
__device__ float g_bufB[(size_t)NCH * PLANE];

// Fragment-layout weights: [layer][kt][mtile][lane] -> uint4 (8 halves, mma A-frag order)
__device__ uint4 WC_hi[7 * 48 * 16 * 32];
__device__ uint4 WC_lo[7 * 48 * 16 * 32];
__device__ uint4 WP_hi[18 * 16 * 32];
__device__ uint4 WP_lo[18 * 16 * 32];

// ---------------------------------------------------------------------------
__device__ __forceinline__ uint32_t smem_u32(const void* p) {
    uint32_t a;
    asm("{ .reg .u64 t; cvta.to.shared.u64 t, %1; cvt.u32.u64 %0, t; }" : "=r"(a) : "l"(p));
    return a;
}
__device__ __forceinline__ float gelu_res(float c) {
    return fmaf(0.5f * c, 1.0f + erff(c * 0.70710678118654752440f), c);
}
__device__ __forceinline__ uint32_t pack_hl(float v) {
    __half hh = __float2half_rn(v);
    float res = v - __half2float(hh);
    return (uint32_t)__half_as_ushort(hh) |
           ((uint32_t)__half_as_ushort(__float2half_rn(res)) << 16);
}
__device__ __forceinline__ void mma16816(float* d, const uint4 a, uint32_t b0, uint32_t b1) {
    asm volatile(
        "mma.sync.aligned.m16n8k16.row.col.f32.f16.f16.f32 "
        "{%0,%1,%2,%3}, {%4,%5,%6,%7}, {%8,%9}, {%0,%1,%2,%3};"
        : "+f"(d[0]), "+f"(d[1]), "+f"(d[2]), "+f"(d[3])
        : "r"(a.x), "r"(a.y), "r"(a.z), "r"(a.w), "r"(b0), "r"(b1));
}
__device__ __forceinline__ void ldmx4(uint32_t& r0, uint32_t& r1, uint32_t& r2, uint32_t& r3,
                                      uint32_t addr) {
    asm volatile("ldmatrix.sync.aligned.m8n8.x4.shared.b16 {%0,%1,%2,%3}, [%4];"
                 : "=r"(r0), "=r"(r1), "=r"(r2), "=r"(r3) : "r"(addr));
}
__device__ __forceinline__ void ldmx4t(uint32_t& r0, uint32_t& r1, uint32_t& r2, uint32_t& r3,
                                       uint32_t addr) {
    asm volatile("ldmatrix.sync.aligned.m8n8.x4.trans.shared.b16 {%0,%1,%2,%3}, [%4];"
                 : "=r"(r0), "=r"(r1), "=r"(r2), "=r"(r3) : "r"(addr));
}
__device__ __forceinline__ uint4 lds128(uint32_t addr) {
    uint4 r;
    asm volatile("ld.shared.v4.u32 {%0,%1,%2,%3}, [%4];"
                 : "=r"(r.x), "=r"(r.y), "=r"(r.z), "=r"(r.w) : "r"(addr));
    return r;
}
__device__ __forceinline__ void cp16(uint32_t dst, const void* src) {
    asm volatile("cp.async.cg.shared.global [%0], [%1], 16;" :: "r"(dst), "l"(src));
}
#define CP_COMMIT() asm volatile("cp.async.commit_group;" ::: "memory")
#define CP_WAIT0()  asm volatile("cp.async.wait_group 0;" ::: "memory")

// ---------------------------------------------------------------------------
// Weight prep: fp32 -> (hi,lo) fp16 in mma A-fragment order.
// ---------------------------------------------------------------------------
__device__ __forceinline__ void split_pack(const float* v, uint4& hi, uint4& lo) {
    uint32_t hx[4], lx[4];
#pragma unroll
    for (int q = 0; q < 4; q++) {
        float a = v[2 * q], b = v[2 * q + 1];
        __half ah = __float2half_rn(a), bh = __float2half_rn(b);
        float ar = a - __half2float(ah), br = b - __half2float(bh);
        hx[q] = (uint32_t)__half_as_ushort(ah) | ((uint32_t)__half_as_ushort(bh) << 16);
        lx[q] = (uint32_t)__half_as_ushort(__float2half_rn(ar)) |
                ((uint32_t)__half_as_ushort(__float2half_rn(br)) << 16);
    }
    hi = make_uint4(hx[0], hx[1], hx[2], hx[3]);
    lo = make_uint4(lx[0], lx[1], lx[2], lx[3]);
}

__global__ void prep_conv_w(const float* __restrict__ tw) {
    int idx = blockIdx.x * 256 + threadIdx.x;
    if (idx >= 7 * 48 * 16 * 32) return;
    int lane = idx & 31;
    int mt = (idx >> 5) & 15;
    int kt = (idx >> 9) % 48;
    int layer = (idx >> 9) / 48;
    int g = lane >> 2, t = lane & 3;
    const float* W = tw + (size_t)layer * 256 * 768;
    int r0 = mt * 16 + g, r1 = r0 + 8;
    int c0 = kt * 16 + 2 * t;
    float v[8];
    v[0] = W[r0 * 768 + c0];     v[1] = W[r0 * 768 + c0 + 1];
    v[2] = W[r1 * 768 + c0];     v[3] = W[r1 * 768 + c0 + 1];
    v[4] = W[r0 * 768 + c0 + 8]; v[5] = W[r0 * 768 + c0 + 9];
    v[6] = W[r1 * 768 + c0 + 8]; v[7] = W[r1 * 768 + c0 + 9];
    split_pack(v, WC_hi[idx], WC_lo[idx]);
}

__global__ void prep_proj_w(const float* __restrict__ wp) {
    int idx = blockIdx.x * 256 + threadIdx.x;
    if (idx >= 18 * 16 * 32) return;
    int lane = idx & 31;
    int mt = (idx >> 5) & 15;
    int kt = idx >> 9;
    int g = lane >> 2, t = lane & 3;
    int r0 = mt * 16 + g, r1 = r0 + 8;
    int c0 = kt * 16 + 2 * t;
    const int cs[4] = {c0, c0 + 1, c0 + 8, c0 + 9};
    float v[8];
    v[0] = (cs[0] < 283) ? wp[r0 * 283 + cs[0]] : 0.f;
    v[1] = (cs[1] < 283) ? wp[r0 * 283 + cs[1]] : 0.f;
    v[2] = (cs[0] < 283) ? wp[r1 * 283 + cs[0]] : 0.f;
    v[3] = (cs[1] < 283) ? wp[r1 * 283 + cs[1]] : 0.f;
    v[4] = (cs[2] < 283) ? wp[r0 * 283 + cs[2]] : 0.f;
    v[5] = (cs[3] < 283) ? wp[r0 * 283 + cs[3]] : 0.f;
    v[6] = (cs[2] < 283) ? wp[r1 * 283 + cs[2]] : 0.f;
    v[7] = (cs[3] < 283) ? wp[r1 * 283 + cs[3]] : 0.f;
    split_pack(v, WP_hi[idx], WP_lo[idx]);
}

// ---------------------------------------------------------------------------
// Projection kernel (R3/R4-validated): C[256co][131072r] = Wp * X^T.
// Writes packed (hi,lo) activations to g_bufA.
// ---------------------------------------------------------------------------
__global__ __launch_bounds__(256, 1) void proj_kernel(const float* __restrict__ xin) {
    constexpr int KT = 18;
    __shared__ unsigned short Bs[2][2][128 * 24];

    const int tid = threadIdx.x;
    const int lane = tid & 31;
    const int wid = tid >> 5;
    const int wm = wid >> 2;
    const int wn = wid & 3;
    const int mbase = blockIdx.y * 128;
    const int rbase = blockIdx.x * 128;

    const int kk = tid & 15;
    const int lrow = tid >> 4;
    uint32_t vr[8];

    auto gather = [&](int kt) {
        int m = kt * 16 + kk;
#pragma unroll
        for (int e = 0; e < 8; e++) {
            float v = 0.f;
            if (m < 283) v = xin[(size_t)(rbase + lrow + e * 16) * 283 + m];
            vr[e] = pack_hl(v);
        }
    };
    auto stsB = [&](int s) {
#pragma unroll
        for (int e = 0; e < 8; e++) {
            int l = lrow + e * 16;
            Bs[s][0][l * 24 + kk] = (unsigned short)(vr[e] & 0xffff);
            Bs[s][1][l * 24 + kk] = (unsigned short)(vr[e] >> 16);
        }
    };

    uint4 Ah[2][4], Al[2][4];
    auto loadA = [&](int kt, int b) {
#pragma unroll
        for (int i = 0; i < 4; i++) {
            int mt = blockIdx.y * 8 + wm * 4 + i;
            size_t o = (size_t)(kt * 16 + mt) * 32 + lane;
            Ah[b][i] = WP_hi[o];
            Al[b][i] = WP_lo[o];
        }
    };

    float acc[4][4][4];
#pragma unroll
    for (int i = 0; i < 4; i++)
#pragma unroll
        for (int j = 0; j < 4; j++)
#pragma unroll
            for (int q = 0; q < 4; q++) acc[i][j][q] = 0.f;

    gather(0); stsB(0); loadA(0, 0);
    __syncthreads();

    const uint32_t sbase = smem_u32(Bs);
    const int rsel = (lane & 7) + ((lane & 16) ? 8 : 0);
    const int csel = (lane & 8) ? 8 : 0;

    auto body = [&](int kt, int s) {
        if (kt + 1 < KT) { gather(kt + 1); loadA(kt + 1, s ^ 1); }
        uint32_t bh[4][2], bl[4][2];
#pragma unroll
        for (int pr = 0; pr < 2; pr++) {
            int row = wn * 32 + pr * 16 + rsel;
            uint32_t ah = sbase + (uint32_t)(((s * 2 + 0) * 3072 + row * 24 + csel) * 2);
            uint32_t al = sbase + (uint32_t)(((s * 2 + 1) * 3072 + row * 24 + csel) * 2);
            uint32_t r0, r1, r2, r3;
            ldmx4(r0, r1, r2, r3, ah);
            bh[pr * 2][0] = r0; bh[pr * 2][1] = r1;
            bh[pr * 2 + 1][0] = r2; bh[pr * 2 + 1][1] = r3;
            ldmx4(r0, r1, r2, r3, al);
            bl[pr * 2][0] = r0; bl[pr * 2][1] = r1;
            bl[pr * 2 + 1][0] = r2; bl[pr * 2 + 1][1] = r3;
        }
#pragma unroll
        for (int i = 0; i < 4; i++)
#pragma unroll
            for (int j = 0; j < 4; j++) {
                mma16816(acc[i][j], Ah[s][i], bh[j][0], bh[j][1]);
                mma16816(acc[i][j], Ah[s][i], bl[j][0], bl[j][1]);
                mma16816(acc[i][j], Al[s][i], bh[j][0], bh[j][1]);
            }
        if (kt + 1 < KT) stsB(s ^ 1);
        __syncthreads();
    };

    for (int kt2 = 0; kt2 < KT; kt2 += 2) { body(kt2, 0); body(kt2 + 1, 1); }

    const int g = lane >> 2, t4 = lane & 3;
    int nn = rbase >> 9;
    int lp0 = rbase & 511;
    uint32_t* outp = (uint32_t*)g_bufA + (size_t)nn * PLANE;
#pragma unroll
    for (int i = 0; i < 4; i++) {
        int co0 = mbase + wm * 64 + i * 16 + g;
#pragma unroll
        for (int j = 0; j < 4; j++) {
            int lp = lp0 + wn * 32 + j * 8 + 2 * t4;
            uint2 v0, v1;
            v0.x = pack_hl(acc[i][j][0]); v0.y = pack_hl(acc[i][j][1]);
            v1.x = pack_hl(acc[i][j][2]); v1.y = pack_hl(acc[i][j][3]);
            *(uint2*)&outp[(size_t)co0 * 512 + lp] = v0;
            *(uint2*)&outp[(size_t)(co0 + 8) * 512 + lp] = v1;
        }
    }
}

// ---------------------------------------------------------------------------
// Conv layer kernel, cp.async A pipeline + 4-slot B ring (1 barrier / 2 kt).
// MODE 1: packed half2 out; MODE 2: fp32 out (last layer). gelu+res epilogue.
// CTA: 256 thr, tile M=128 x N=128, K-tile 16, 48 tiles, 2 CTAs/SM.
// Dynamic smem: A 4 slots x 8192B | B 8 planes x 4352B  = 67584B.
// ---------------------------------------------------------------------------
#define SSTR 136                 // halves per k-row (128 + 8 pad)
#define A_REG 32768
#define B_PLANE 4352
#define SMEM_CONV (A_REG + 8 * B_PLANE)

__device__ __forceinline__ uint2 ld2_guard(const uint32_t* row, int base) {
    if ((unsigned)base <= 510u) return *(const uint2*)(row + base);
    uint2 r;
    r.x = ((unsigned)(base)     < 512u) ? row[base]     : 0u;
    r.y = ((unsigned)(base + 1) < 512u) ? row[base + 1] : 0u;
    return r;
}

template <int MODE, bool A2B>
__global__ __launch_bounds__(256, 2) void conv_kernel(
    const float* __restrict__ bias, int dil, int layer)
{
    extern __shared__ char dsm[];
    const uint32_t sm0 = smem_u32(dsm);
    const uint32_t sA = sm0;                 // A slots
    const uint32_t sB = sm0 + A_REG;         // B planes
    char* bptr = dsm + A_REG;

    const int tid = threadIdx.x;
    const int lane = tid & 31;
    const int wid = tid >> 5;
    const int wm = wid >> 2;      // 0..1
    const int wn = wid & 3;       // 0..3
    const int mbase = blockIdx.y * 128;
    const int mt8 = blockIdx.y * 8;
    const int n = blockIdx.z;
    const int l0 = blockIdx.x * 128;

    const uint4* __restrict__ WAhi = WC_hi + (size_t)layer * 48 * 16 * 32;
    const uint4* __restrict__ WAlo = WC_lo + (size_t)layer * 48 * 16 * 32;
    const uint32_t* __restrict__ inw =
        (const uint32_t*)(A2B ? g_bufA : g_bufB) + (size_t)n * PLANE;

    // A cp.async: 256 threads x (hi 16B + lo 16B) per kt
    const int amt = tid >> 5;                  // 0..7 local mtile
    auto cpA = [&](int kt, int q) {
        size_t src = (size_t)(kt * 16 + mt8 + amt) * 32 + lane;
        uint32_t d = sA + q * 8192 + tid * 16;
        cp16(d, WAhi + src);
        cp16(d + 4096, WAlo + src);
    };

    // B gather: thread -> (k-row kk, 8 consecutive l at ll0)
    const int kk = tid >> 4;
    const int ll0 = (tid & 15) * 8;
    uint2 v[4];
    auto gather = [&](int kt) {
        int kg = kt * 16 + kk;
        int ci = kg / 3;
        int sh = (kg - 3 * ci - 1) * dil;
        const uint32_t* rowp = inw + ci * 512;
        int base = l0 + ll0 + sh;
        v[0] = ld2_guard(rowp, base);
        v[1] = ld2_guard(rowp, base + 2);
        v[2] = ld2_guard(rowp, base + 4);
        v[3] = ld2_guard(rowp, base + 6);
    };
    auto stsB = [&](int q) {
        uint4 hv, lv;
        hv.x = (v[0].x & 0xffffu) | (v[0].y << 16);
        hv.y = (v[1].x & 0xffffu) | (v[1].y << 16);
        hv.z = (v[2].x & 0xffffu) | (v[2].y << 16);
        hv.w = (v[3].x & 0xffffu) | (v[3].y << 16);
        lv.x = (v[0].x >> 16) | (v[0].y & 0xffff0000u);
        lv.y = (v[1].x >> 16) | (v[1].y & 0xffff0000u);
        lv.z = (v[2].x >> 16) | (v[2].y & 0xffff0000u);
        lv.w = (v[3].x >> 16) | (v[3].y & 0xffff0000u);
        *(uint4*)(bptr + (q * 2 + 0) * B_PLANE + (kk * SSTR + ll0) * 2) = hv;
        *(uint4*)(bptr + (q * 2 + 1) * B_PLANE + (kk * SSTR + ll0) * 2) = lv;
    };

    float acc[4][4][4];
#pragma unroll
    for (int i = 0; i < 4; i++)
#pragma unroll
        for (int j = 0; j < 4; j++)
#pragma unroll
            for (int q = 0; q < 4; q++) acc[i][j][q] = 0.f;

    // ldmatrix.trans lane addressing (identical to R4)
    const int grp = lane >> 3, lwi = lane & 7;
    const int krow = (grp & 1) * 8 + lwi;
    const int ncol = wn * 32 + (grp >> 1) * 8;

    auto mma_block = [&](int q) {
        uint32_t ph = sB + (uint32_t)(q * 2 + 0) * B_PLANE;
        uint32_t pl = sB + (uint32_t)(q * 2 + 1) * B_PLANE;
        uint32_t bh[4][2], bl[4][2];
#pragma unroll
        for (int jj = 0; jj < 2; jj++) {
            uint32_t r0, r1, r2, r3;
            ldmx4t(r0, r1, r2, r3, ph + (uint32_t)((krow * SSTR + ncol + jj * 16) * 2));
            bh[jj * 2][0] = r0;     bh[jj * 2][1] = r1;
            bh[jj * 2 + 1][0] = r2; bh[jj * 2 + 1][1] = r3;
            ldmx4t(r0, r1, r2, r3, pl + (uint32_t)((krow * SSTR + ncol + jj * 16) * 2));
            bl[jj * 2][0] = r0;     bl[jj * 2][1] = r1;
            bl[jj * 2 + 1][0] = r2; bl[jj * 2 + 1][1] = r3;
        }
        uint32_t abase = sA + (uint32_t)q * 8192;
#pragma unroll
        for (int ih = 0; ih < 4; ih += 2) {
            uint4 Ah[2], Al[2];
#pragma unroll
            for (int u = 0; u < 2; u++) {
                uint32_t ao = abase + (uint32_t)(((wm * 4 + ih + u) * 32 + lane) * 16);
                Ah[u] = lds128(ao);
                Al[u] = lds128(ao + 4096);
            }
#pragma unroll
            for (int u = 0; u < 2; u++)
#pragma unroll
                for (int j = 0; j < 4; j++) {
                    mma16816(acc[ih + u][j], Ah[u], bh[j][0], bh[j][1]);
                    mma16816(acc[ih + u][j], Ah[u], bl[j][0], bl[j][1]);
                    mma16816(acc[ih + u][j], Al[u], bh[j][0], bh[j][1]);
                }
        }
    };

    // prologue: fill slots 0,1
    cpA(0, 0); cpA(1, 1); CP_COMMIT();
    gather(0); stsB(0);
    gather(1); stsB(1);
    CP_WAIT0();
    __syncthreads();

    int qc = 0;
    for (int kt2 = 0; kt2 < 48; kt2 += 2) {
        const int qn = qc ^ 2;
        const bool more = (kt2 + 2) < 48;
        if (more) { cpA(kt2 + 2, qn); cpA(kt2 + 3, qn + 1); CP_COMMIT(); }
        if (more) gather(kt2 + 2);
        mma_block(qc);
        if (more) stsB(qn);
        if (more) gather(kt2 + 3);
        mma_block(qc + 1);
        if (more) stsB(qn + 1);
        CP_WAIT0();
        __syncthreads();
        qc = qn;
    }

    // ---- epilogue ----
    const int g = lane >> 2, t4 = lane & 3;
    if (MODE == 1) {
        uint32_t* outp = (uint32_t*)(A2B ? g_bufB : g_bufA) + (size_t)n * PLANE;
#pragma unroll
        for (int i = 0; i < 4; i++) {
            int co0 = mbase + wm * 64 + i * 16 + g;
            float b0 = bias[co0], b1 = bias[co0 + 8];
#pragma unroll
            for (int j = 0; j < 4; j++) {
                int lp = l0 + wn * 32 + j * 8 + 2 * t4;
                uint2 v0, v1;
                v0.x = pack_hl(gelu_res(acc[i][j][0] + b0));
                v0.y = pack_hl(gelu_res(acc[i][j][1] + b0));
                v1.x = pack_hl(gelu_res(acc[i][j][2] + b1));
                v1.y = pack_hl(gelu_res(acc[i][j][3] + b1));
                *(uint2*)&outp[(size_t)co0 * 512 + lp] = v0;
                *(uint2*)&outp[(size_t)(co0 + 8) * 512 + lp] = v1;
            }
        }
    } else {
        float* outp = (A2B ? g_bufB : g_bufA) + (size_t)n * PLANE;
#pragma unroll
        for (int i = 0; i < 4; i++) {
            int co0 = mbase + wm * 64 + i * 16 + g;
            float b0 = bias[co0], b1 = bias[co0 + 8];
#pragma unroll
            for (int j = 0; j < 4; j++) {
                int lp = l0 + wn * 32 + j * 8 + 2 * t4;
                float2 v0, v1;
                v0.x = gelu_res(acc[i][j][0] + b0);
                v0.y = gelu_res(acc[i][j][1] + b0);
                v1.x = gelu_res(acc[i][j][2] + b1);
                v1.y = gelu_res(acc[i][j][3] + b1);
                *(float2*)&outp[(size_t)co0 * 512 + lp] = v0;
                *(float2*)&outp[(size_t)(co0 + 8) * 512 + lp] = v1;
            }
        }
    }
}

// ---------------------------------------------------------------------------
// Head: profile conv (K=20, pad (9,10)) + mean pool + atpm, fused.
// Double-buffered channel row: 1 barrier per c, load latency hidden.
// ---------------------------------------------------------------------------
__global__ __launch_bounds__(512) void head_kernel(const float* __restrict__ wprof,
                                                   const float* __restrict__ bprof,
                                                   const float* __restrict__ watpm,
                                                   const float* __restrict__ batpm,
                                                   const int* __restrict__ np_raw,
                                                   float* __restrict__ out) {
    __shared__ float buf[2][544];
    __shared__ float wp[HID * 20];
    __shared__ float wa[HID];
    __shared__ float red[16];

    const int n = blockIdx.x;
    const int tid = threadIdx.x;
    const float* h = g_bufB + (size_t)n * PLANE;

    for (int i = tid; i < HID * 20; i += 512) wp[i] = wprof[i];
    if (tid < HID) wa[tid] = watpm[tid];
    if (tid < 9)  { buf[0][tid] = 0.f; buf[1][tid] = 0.f; }
    if (tid < 13) { buf[0][521 + tid] = 0.f; buf[1][521 + tid] = 0.f; }

    float accp = 0.f, acca = 0.f;
    buf[0][9 + tid] = h[tid];
    __syncthreads();

    for (int c = 0; c < HID; c++) {
        const int cur = c & 1;
        if (c + 1 < HID) buf[cur ^ 1][9 + tid] = h[(c + 1) * LC + tid];
        acca = fmaf(buf[cur][9 + tid], wa[c], acca);
        const float* wr = &wp[c * 20];
#pragma unroll
        for (int k = 0; k < 20; k++)
            accp = fmaf(buf[cur][tid + k], wr[k], accp);
        __syncthreads();
    }

    out[256 + n * LC + tid] = accp + bprof[0];

#pragma unroll
    for (int o = 16; o > 0; o >>= 1) acca += __shfl_xor_sync(0xffffffffu, acca, o);
    if ((tid & 31) == 0) red[tid >> 5] = acca;
    __syncthreads();
    if (tid < 16) {
        float vv = red[tid];
#pragma unroll
        for (int o = 8; o > 0; o >>= 1) vv += __shfl_xor_sync(0x0000ffffu, vv, o);
        if (tid == 0) {
            int n0 = np_raw[0];
            int n1;
            int w1 = np_raw[1];
            if (w1 != 0) {
                n1 = w1;
            } else {
                int w2 = np_raw[2], w3 = np_raw[3];
                n1 = (w2 >= 0 && w2 < 128 && w3 == 0) ? w2 : 0;
            }
            float atpm = vv * (1.0f / 512.0f) + batpm[0];
            int p = n & 127, b = n >> 7;
            int lim = (b == 0) ? n0 : n1;
            out[n] = (p < lim) ? atpm : 0.f;
        }
    }
}

// ---------------------------------------------------------------------------
extern "C" void kernel_launch(void* const* d_in, const int* in_sizes, int n_in,
                              void* d_out, int out_size) {
    const float* x       = (const float*)d_in[0];
    const float* w_proj  = (const float*)d_in[1];
    const float* tower_w = (const float*)d_in[2];
    const float* tower_b = (const float*)d_in[3];
    const float* w_prof  = (const float*)d_in[4];
    const float* b_prof  = (const float*)d_in[5];
    const float* w_atpm  = (const float*)d_in[6];
    const float* b_atpm  = (const float*)d_in[7];
    const int*   n_peaks = (const int*)d_in[8];
    float* out = (float*)d_out;

    (void)in_sizes; (void)n_in; (void)out_size;

    cudaFuncSetAttribute(conv_kernel<1, true>,
                         cudaFuncAttributeMaxDynamicSharedMemorySize, SMEM_CONV);
    cudaFuncSetAttribute(conv_kernel<1, false>,
                         cudaFuncAttributeMaxDynamicSharedMemorySize, SMEM_CONV);
    cudaFuncSetAttribute(conv_kernel<2, true>,
                         cudaFuncAttributeMaxDynamicSharedMemorySize, SMEM_CONV);

    // 0) weight prep (fragment layout + fp16 hi/lo split)
    prep_conv_w<<<672, 256>>>(tower_w);
    prep_proj_w<<<36, 256>>>(w_proj);

    // 1) projection -> g_bufA (packed half2 hi/lo)
    proj_kernel<<<dim3(1024, 2, 1), 256>>>(x);

    // 2) conv tower, ping-pong; layer 6 writes fp32 into g_bufB
    dim3 gc(4, 2, NCH);
    for (int i = 0; i < 7; i++) {
        int dil = 2 << i;
        const float* bl = tower_b + (size_t)i * HID;
        if (i == 6)            conv_kernel<2, true ><<<gc, 256, SMEM_CONV>>>(bl, dil, i);
        else if ((i & 1) == 0) conv_kernel<1, true ><<<gc, 256, SMEM_CONV>>>(bl, dil, i);
        else                   conv_kernel<1, false><<<gc, 256, SMEM_CONV>>>(bl, dil, i);
    }

    // 3) fused heads from g_bufB
    head_kernel<<<NCH, 512>>>(w_prof, b_prof, w_atpm, b_atpm, n_peaks, out);
}